// round 1
// baseline (speedup 1.0000x reference)
#include <cuda_runtime.h>
#include <math.h>

#define SEQ 8192
#define DIM 768

// Scratch (allocation-free rule: __device__ globals)
__device__ float g_Q[SEQ * DIM];
__device__ float g_K[SEQ * DIM];
__device__ float g_V[SEQ * DIM];
__device__ float g_S[(size_t)SEQ * SEQ];   // 268 MB score matrix

// ---------------------------------------------------------------------------
// Tiled fp32 GEMM, 128x128 block tile, K-tile 16, 256 threads, 8x8 per thread.
// BT=1: C[m,n] = alpha * sum_k A[m,k] * B[n,k]   (B is [N,K], "NT")
// BT=0: C[m,n] = alpha * sum_k A[m,k] * B[k,n]   (B is [K,N], "NN")
// Requires M%128==0, N%128==0, K%16==0 (true for all our shapes).
// ---------------------------------------------------------------------------
template <int BT>
__global__ void __launch_bounds__(256)
gemm_tile(const float* __restrict__ A, const float* __restrict__ B,
          float* __restrict__ C, int M, int N, int K, float alpha)
{
    __shared__ float As[16][128];
    __shared__ float Bs[16][128];

    const int tid = threadIdx.x;
    const int bm  = blockIdx.y * 128;
    const int bn  = blockIdx.x * 128;
    const int tx  = tid & 15;   // 0..15 -> n fragment
    const int ty  = tid >> 4;   // 0..15 -> m fragment

    float acc[8][8];
#pragma unroll
    for (int i = 0; i < 8; i++)
#pragma unroll
        for (int j = 0; j < 8; j++) acc[i][j] = 0.f;

    for (int k0 = 0; k0 < K; k0 += 16) {
        // ---- load A tile: 128 rows x 16 k  (A is [M,K], K-contiguous) ----
#pragma unroll
        for (int i = 0; i < 2; i++) {
            int v   = tid + i * 256;        // 0..511 float4 slots
            int row = v >> 2;               // 0..127
            int c4  = (v & 3) << 2;         // 0,4,8,12
            float4 a = *(const float4*)(A + (size_t)(bm + row) * K + k0 + c4);
            As[c4 + 0][row] = a.x;
            As[c4 + 1][row] = a.y;
            As[c4 + 2][row] = a.z;
            As[c4 + 3][row] = a.w;
        }
        // ---- load B tile ----
        if (BT) {
            // B is [N,K]: mirror of A load
#pragma unroll
            for (int i = 0; i < 2; i++) {
                int v   = tid + i * 256;
                int row = v >> 2;
                int c4  = (v & 3) << 2;
                float4 b = *(const float4*)(B + (size_t)(bn + row) * K + k0 + c4);
                Bs[c4 + 0][row] = b.x;
                Bs[c4 + 1][row] = b.y;
                Bs[c4 + 2][row] = b.z;
                Bs[c4 + 3][row] = b.w;
            }
        } else {
            // B is [K,N]: 16 rows x 128 n, directly vectorized
#pragma unroll
            for (int i = 0; i < 2; i++) {
                int v  = tid + i * 256;     // 0..511 float4 slots
                int kr = v >> 5;            // 0..15
                int c4 = (v & 31) << 2;     // 0..124
                float4 b = *(const float4*)(B + (size_t)(k0 + kr) * N + bn + c4);
                *(float4*)&Bs[kr][c4] = b;
            }
        }
        __syncthreads();

        // ---- compute ----
#pragma unroll
        for (int k = 0; k < 16; k++) {
            float4 a0 = *(const float4*)&As[k][ty * 8];
            float4 a1 = *(const float4*)&As[k][ty * 8 + 4];
            float4 b0 = *(const float4*)&Bs[k][tx * 8];
            float4 b1 = *(const float4*)&Bs[k][tx * 8 + 4];
            float ra[8] = {a0.x, a0.y, a0.z, a0.w, a1.x, a1.y, a1.z, a1.w};
            float rb[8] = {b0.x, b0.y, b0.z, b0.w, b1.x, b1.y, b1.z, b1.w};
#pragma unroll
            for (int i = 0; i < 8; i++)
#pragma unroll
                for (int j = 0; j < 8; j++)
                    acc[i][j] = fmaf(ra[i], rb[j], acc[i][j]);
        }
        __syncthreads();
    }

    // ---- epilogue ----
#pragma unroll
    for (int i = 0; i < 8; i++) {
        int m = bm + ty * 8 + i;
        float4 o0 = make_float4(acc[i][0] * alpha, acc[i][1] * alpha,
                                acc[i][2] * alpha, acc[i][3] * alpha);
        float4 o1 = make_float4(acc[i][4] * alpha, acc[i][5] * alpha,
                                acc[i][6] * alpha, acc[i][7] * alpha);
        *(float4*)(C + (size_t)m * N + bn + tx * 8)     = o0;
        *(float4*)(C + (size_t)m * N + bn + tx * 8 + 4) = o1;
    }
}

// ---------------------------------------------------------------------------
// Row softmax over g_S: one block per row, row cached in shared memory.
// ---------------------------------------------------------------------------
__global__ void __launch_bounds__(256) softmax_rows(float* __restrict__ S)
{
    __shared__ float buf[SEQ];      // 32 KB row cache
    __shared__ float red[256];

    const size_t base = (size_t)blockIdx.x * SEQ;
    const int tid = threadIdx.x;

    // pass 1: load + local max
    float lmax = -INFINITY;
    for (int i = tid; i < SEQ / 4; i += 256) {
        float4 v = *(const float4*)(S + base + (size_t)i * 4);
        *(float4*)&buf[i * 4] = v;
        lmax = fmaxf(lmax, fmaxf(fmaxf(v.x, v.y), fmaxf(v.z, v.w)));
    }
    red[tid] = lmax;
    __syncthreads();
#pragma unroll
    for (int s = 128; s > 0; s >>= 1) {
        if (tid < s) red[tid] = fmaxf(red[tid], red[tid + s]);
        __syncthreads();
    }
    const float m = red[0];
    __syncthreads();

    // pass 2: exp + local sum
    float lsum = 0.f;
    for (int i = tid; i < SEQ / 4; i += 256) {
        float4 v = *(const float4*)&buf[i * 4];
        v.x = __expf(v.x - m);
        v.y = __expf(v.y - m);
        v.z = __expf(v.z - m);
        v.w = __expf(v.w - m);
        *(float4*)&buf[i * 4] = v;
        lsum += v.x + v.y + v.z + v.w;
    }
    red[tid] = lsum;
    __syncthreads();
#pragma unroll
    for (int s = 128; s > 0; s >>= 1) {
        if (tid < s) red[tid] += red[tid + s];
        __syncthreads();
    }
    const float inv = 1.f / red[0];
    __syncthreads();

    // pass 3: scale + store
    for (int i = tid; i < SEQ / 4; i += 256) {
        float4 v = *(const float4*)&buf[i * 4];
        v.x *= inv; v.y *= inv; v.z *= inv; v.w *= inv;
        *(float4*)(S + base + (size_t)i * 4) = v;
    }
}

// ---------------------------------------------------------------------------
extern "C" void kernel_launch(void* const* d_in, const int* in_sizes, int n_in,
                              void* d_out, int out_size)
{
    const float* X  = (const float*)d_in[0];   // [SEQ, DIM]
    const float* Wq = (const float*)d_in[1];   // [DIM, DIM]
    const float* Wk = (const float*)d_in[2];
    const float* Wv = (const float*)d_in[3];
    float* O = (float*)d_out;                  // [SEQ, DIM] fp32

    float *Q, *K_, *V, *S;
    cudaGetSymbolAddress((void**)&Q,  g_Q);
    cudaGetSymbolAddress((void**)&K_, g_K);
    cudaGetSymbolAddress((void**)&V,  g_V);
    cudaGetSymbolAddress((void**)&S,  g_S);

    const dim3 blk(256);
    const dim3 gproj(DIM / 128, SEQ / 128);    // 6 x 64
    const dim3 gS(SEQ / 128, SEQ / 128);       // 64 x 64
    const dim3 gPV(DIM / 128, SEQ / 128);      // 6 x 64
    const float inv_sqrt_d = 0.03608439182435161f;  // 1/sqrt(768)

    // QKV projections: y = x @ W^T  -> NT gemm
    gemm_tile<1><<<gproj, blk>>>(X, Wq, Q,  SEQ, DIM, DIM, 1.f);
    gemm_tile<1><<<gproj, blk>>>(X, Wk, K_, SEQ, DIM, DIM, 1.f);
    gemm_tile<1><<<gproj, blk>>>(X, Wv, V,  SEQ, DIM, DIM, 1.f);

    // S = (Q @ K^T) / sqrt(d)  -> NT gemm
    gemm_tile<1><<<gS, blk>>>(Q, K_, S, SEQ, SEQ, DIM, inv_sqrt_d);

    // row softmax
    softmax_rows<<<SEQ, blk>>>(S);

    // O = P @ V  -> NN gemm
    gemm_tile<0><<<gPV, blk>>>(S, V, O, SEQ, DIM, SEQ, 1.f);
}

// round 3
// speedup vs baseline: 3.0654x; 3.0654x over previous
#include <cuda_runtime.h>
#include <cuda_fp16.h>
#include <math.h>
#include <stdint.h>

#define SEQ 8192
#define DIM 768
#define KE_PROJ (3 * DIM)   // 2304  (split-fp16 tripled K)
#define KE_PV   (3 * SEQ)   // 24576

// ---------------- scratch (__device__ globals; no allocations allowed) -----
__device__ __align__(128) __half g_X3 [(size_t)SEQ * KE_PROJ];
__device__ __align__(128) __half g_Wq3[(size_t)DIM * KE_PROJ];
__device__ __align__(128) __half g_Wk3[(size_t)DIM * KE_PROJ];
__device__ __align__(128) __half g_Wv3[(size_t)DIM * KE_PROJ];
__device__ __align__(128) float  g_Q  [(size_t)SEQ * DIM];
__device__ __align__(128) float  g_K  [(size_t)SEQ * DIM];
__device__ __align__(128) float  g_V  [(size_t)SEQ * DIM];
__device__ __align__(128) __half g_Q3 [(size_t)SEQ * KE_PROJ];
__device__ __align__(128) __half g_K3 [(size_t)SEQ * KE_PROJ];
__device__ __align__(128) __half g_V3t[(size_t)DIM * KE_PV];
__device__ __align__(128) float  g_S  [(size_t)SEQ * SEQ];
__device__ __align__(128) __half g_P3 [(size_t)SEQ * KE_PV];

// ---------------- helpers ----------------------------------------------------
__device__ __forceinline__ uint32_t smem_u32(const void* p) {
    uint32_t a;
    asm("{ .reg .u64 t; cvta.to.shared.u64 t, %1; cvt.u32.u64 %0, t; }"
        : "=r"(a) : "l"(p));
    return a;
}

#define MMA16816(d, a, b0, b1)                                                 \
    asm volatile(                                                              \
        "mma.sync.aligned.m16n8k16.row.col.f32.f16.f16.f32 "                   \
        "{%0,%1,%2,%3}, {%4,%5,%6,%7}, {%8,%9}, {%0,%1,%2,%3};"                \
        : "+f"((d)[0]), "+f"((d)[1]), "+f"((d)[2]), "+f"((d)[3])               \
        : "r"((a)[0]), "r"((a)[1]), "r"((a)[2]), "r"((a)[3]),                  \
          "r"(b0), "r"(b1))

#define LDSM_X4(r, addr)                                                       \
    asm volatile("ldmatrix.sync.aligned.m8n8.x4.shared.b16 {%0,%1,%2,%3}, [%4];" \
        : "=r"((r)[0]), "=r"((r)[1]), "=r"((r)[2]), "=r"((r)[3]) : "r"(addr))

#define CP_ASYNC16(saddr, gptr)                                                \
    asm volatile("cp.async.cg.shared.global [%0], [%1], 16;"                   \
        :: "r"(saddr), "l"(gptr))

// ---------------- GEMM: C[M,N] = alpha * A[M,Ke] * B[N,Ke]^T  (fp16 in, fp32 out)
// CTA tile 128x128, BK=64 halves, 8 warps each 32x64, double-buffered cp.async.
#define BM 128
#define BN 128
#define BKH 64                    // halves per K tile (128 bytes per row)
#define TILE_BYTES (128 * 128)    // 16 KB per operand stage
#define GEMM_SMEM (4 * TILE_BYTES) // 64 KB

__global__ void __launch_bounds__(256, 2)
gemm_f16_mma(const __half* __restrict__ A, const __half* __restrict__ B,
             float* __restrict__ C, int M, int N, int Ke, float alpha)
{
    extern __shared__ char smem[];
    const uint32_t sA = smem_u32(smem);                 // 2 stages A
    const uint32_t sB = sA + 2 * TILE_BYTES;            // 2 stages B

    const int tid  = threadIdx.x;
    const int lane = tid & 31;
    const int wid  = tid >> 5;
    const int warp_m = (wid & 3) * 32;
    const int warp_n = (wid >> 2) * 64;
    const int bm = blockIdx.y * BM;
    const int bn = blockIdx.x * BN;
    const int nk = Ke / BKH;

    float acc[2][8][4];
#pragma unroll
    for (int i = 0; i < 2; ++i)
#pragma unroll
        for (int j = 0; j < 8; ++j)
#pragma unroll
            for (int k = 0; k < 4; ++k) acc[i][j][k] = 0.f;

    // loader geometry: 1024 16B-chunks per operand stage; thread covers 4
    const int lr  = tid >> 1;                 // base row helper (unused direct)
    (void)lr;

#define LOAD_STAGE(kt, st)                                                     \
    do {                                                                       \
        _Pragma("unroll")                                                      \
        for (int i = 0; i < 4; ++i) {                                          \
            int idx = tid + i * 256;                                           \
            int row = idx >> 3;                                                \
            int ch  = idx & 7;                                                 \
            int pch = ch ^ (row & 7);                                          \
            const __half* gA = A + (size_t)(bm + row) * Ke + (kt) * BKH + ch * 8; \
            CP_ASYNC16(sA + (st) * TILE_BYTES + row * 128 + pch * 16, gA);     \
            const __half* gB = B + (size_t)(bn + row) * Ke + (kt) * BKH + ch * 8; \
            CP_ASYNC16(sB + (st) * TILE_BYTES + row * 128 + pch * 16, gB);     \
        }                                                                      \
        asm volatile("cp.async.commit_group;");                                \
    } while (0)

    LOAD_STAGE(0, 0);

    for (int kt = 0; kt < nk; ++kt) {
        const int st = kt & 1;
        if (kt + 1 < nk) {
            LOAD_STAGE(kt + 1, st ^ 1);
            asm volatile("cp.async.wait_group 1;");
        } else {
            asm volatile("cp.async.wait_group 0;");
        }
        __syncthreads();

        const uint32_t aBase = sA + st * TILE_BYTES;
        const uint32_t bBase = sB + st * TILE_BYTES;
#pragma unroll
        for (int ks = 0; ks < 4; ++ks) {
            uint32_t af[2][4];
#pragma unroll
            for (int mt = 0; mt < 2; ++mt) {
                int row = warp_m + mt * 16 + (lane & 7) + ((lane >> 3) & 1) * 8;
                int ch  = ks * 2 + (lane >> 4);
                uint32_t ad = aBase + row * 128 + ((ch ^ (row & 7)) * 16);
                LDSM_X4(af[mt], ad);
            }
#pragma unroll
            for (int ng = 0; ng < 4; ++ng) {
                int nrow = warp_n + ng * 16 + (lane & 7) + ((lane >> 4) & 1) * 8;
                int ch   = ks * 2 + ((lane >> 3) & 1);
                uint32_t bd = bBase + nrow * 128 + ((ch ^ (nrow & 7)) * 16);
                uint32_t bf[4];
                LDSM_X4(bf, bd);
#pragma unroll
                for (int mt = 0; mt < 2; ++mt) {
                    MMA16816(acc[mt][ng * 2],     af[mt], bf[0], bf[1]);
                    MMA16816(acc[mt][ng * 2 + 1], af[mt], bf[2], bf[3]);
                }
            }
        }
        __syncthreads();
    }

    // epilogue: fragment -> global fp32
#pragma unroll
    for (int mt = 0; mt < 2; ++mt) {
        const int r0 = bm + warp_m + mt * 16 + (lane >> 2);
#pragma unroll
        for (int nt = 0; nt < 8; ++nt) {
            const int c = bn + warp_n + nt * 8 + (lane & 3) * 2;
            float2 v0 = make_float2(acc[mt][nt][0] * alpha, acc[mt][nt][1] * alpha);
            float2 v1 = make_float2(acc[mt][nt][2] * alpha, acc[mt][nt][3] * alpha);
            *(float2*)(C + (size_t)r0 * N + c)       = v0;
            *(float2*)(C + (size_t)(r0 + 8) * N + c) = v1;
        }
    }
#undef LOAD_STAGE
}

// ---------------- fp32 -> split-fp16 panel conversions ----------------------
__device__ __forceinline__ uint32_t pack2(__half a, __half b) {
    __half2 h = __halves2half2(a, b);
    return *(uint32_t*)&h;
}

// LOPANEL: which of 3 panels holds the low part (A layout: 1, B layout: 2)
template <int LOPANEL>
__global__ void __launch_bounds__(256)
conv_split(const float* __restrict__ src, __half* __restrict__ dst, int rows, int K)
{
    const size_t n4 = (size_t)rows * K / 4;
    const int k4 = K / 4;
    for (size_t i = (size_t)blockIdx.x * 256 + threadIdx.x; i < n4;
         i += (size_t)gridDim.x * 256) {
        const size_t r = i / k4;
        const int c = (int)(i % k4) * 4;
        float4 v = *(const float4*)(src + r * K + c);
        __half h0 = __float2half_rn(v.x), h1 = __float2half_rn(v.y);
        __half h2 = __float2half_rn(v.z), h3 = __float2half_rn(v.w);
        __half l0 = __float2half_rn(v.x - __half2float(h0));
        __half l1 = __float2half_rn(v.y - __half2float(h1));
        __half l2 = __float2half_rn(v.z - __half2float(h2));
        __half l3 = __float2half_rn(v.w - __half2float(h3));
        uint2 hu = make_uint2(pack2(h0, h1), pack2(h2, h3));
        uint2 lu = make_uint2(pack2(l0, l1), pack2(l2, l3));
        __half* d = dst + r * (size_t)(3 * K) + c;
        if (LOPANEL == 1) {
            *(uint2*)(d)         = hu;
            *(uint2*)(d + K)     = lu;
            *(uint2*)(d + 2 * K) = hu;
        } else {
            *(uint2*)(d)         = hu;
            *(uint2*)(d + K)     = hu;
            *(uint2*)(d + 2 * K) = lu;
        }
    }
}

// transpose + split for V: src[R,C] fp32 -> dst[C, 3R] panels (hi, hi, lo)
__global__ void __launch_bounds__(256)
conv_split_trans(const float* __restrict__ src, __half* __restrict__ dst, int R, int C)
{
    __shared__ float t[32][33];
    const int tx = threadIdx.x & 31, ty = threadIdx.x >> 5;
    const int bx = blockIdx.x, by = blockIdx.y;
#pragma unroll
    for (int j = 0; j < 32; j += 8)
        t[ty + j][tx] = src[(size_t)(by * 32 + ty + j) * C + bx * 32 + tx];
    __syncthreads();
#pragma unroll
    for (int j = 0; j < 32; j += 8) {
        float v = t[tx][ty + j];
        __half h = __float2half_rn(v);
        __half l = __float2half_rn(v - __half2float(h));
        __half* d = dst + (size_t)(bx * 32 + ty + j) * (3 * R) + by * 32 + tx;
        d[0]     = h;
        d[R]     = h;
        d[2 * R] = l;
    }
}

// ---------------- softmax over S rows, emitting split-fp16 P panels (hi,lo,hi)
__global__ void __launch_bounds__(256)
softmax_split(const float* __restrict__ S, __half* __restrict__ P3)
{
    __shared__ float buf[SEQ];
    __shared__ float red[256];
    const size_t base = (size_t)blockIdx.x * SEQ;
    const int tid = threadIdx.x;

    float lmax = -INFINITY;
    for (int i = tid; i < SEQ / 4; i += 256) {
        float4 v = *(const float4*)(S + base + (size_t)i * 4);
        *(float4*)&buf[i * 4] = v;
        lmax = fmaxf(lmax, fmaxf(fmaxf(v.x, v.y), fmaxf(v.z, v.w)));
    }
    red[tid] = lmax;
    __syncthreads();
#pragma unroll
    for (int s = 128; s > 0; s >>= 1) {
        if (tid < s) red[tid] = fmaxf(red[tid], red[tid + s]);
        __syncthreads();
    }
    const float m = red[0];
    __syncthreads();

    float lsum = 0.f;
    for (int i = tid; i < SEQ / 4; i += 256) {
        float4 v = *(const float4*)&buf[i * 4];
        v.x = __expf(v.x - m); v.y = __expf(v.y - m);
        v.z = __expf(v.z - m); v.w = __expf(v.w - m);
        *(float4*)&buf[i * 4] = v;
        lsum += v.x + v.y + v.z + v.w;
    }
    red[tid] = lsum;
    __syncthreads();
#pragma unroll
    for (int s = 128; s > 0; s >>= 1) {
        if (tid < s) red[tid] += red[tid + s];
        __syncthreads();
    }
    const float inv = 1.f / red[0];
    __syncthreads();

    __half* d = P3 + (size_t)blockIdx.x * KE_PV;
    for (int i = tid; i < SEQ / 4; i += 256) {
        float4 v = *(const float4*)&buf[i * 4];
        v.x *= inv; v.y *= inv; v.z *= inv; v.w *= inv;
        __half h0 = __float2half_rn(v.x), h1 = __float2half_rn(v.y);
        __half h2 = __float2half_rn(v.z), h3 = __float2half_rn(v.w);
        __half l0 = __float2half_rn(v.x - __half2float(h0));
        __half l1 = __float2half_rn(v.y - __half2float(h1));
        __half l2 = __float2half_rn(v.z - __half2float(h2));
        __half l3 = __float2half_rn(v.w - __half2float(h3));
        uint2 hu = make_uint2(pack2(h0, h1), pack2(h2, h3));
        uint2 lu = make_uint2(pack2(l0, l1), pack2(l2, l3));
        *(uint2*)(d + i * 4)            = hu;   // panel 0: hi
        *(uint2*)(d + SEQ + i * 4)      = lu;   // panel 1: lo
        *(uint2*)(d + 2 * SEQ + i * 4)  = hu;   // panel 2: hi
    }
}

// ---------------------------------------------------------------------------
extern "C" void kernel_launch(void* const* d_in, const int* in_sizes, int n_in,
                              void* d_out, int out_size)
{
    const float* X  = (const float*)d_in[0];
    const float* Wq = (const float*)d_in[1];
    const float* Wk = (const float*)d_in[2];
    const float* Wv = (const float*)d_in[3];
    float* O = (float*)d_out;

    __half *X3, *Wq3, *Wk3, *Wv3, *Q3, *K3, *V3t, *P3;
    float *Q, *K_, *V, *S;
    cudaGetSymbolAddress((void**)&X3,  g_X3);
    cudaGetSymbolAddress((void**)&Wq3, g_Wq3);
    cudaGetSymbolAddress((void**)&Wk3, g_Wk3);
    cudaGetSymbolAddress((void**)&Wv3, g_Wv3);
    cudaGetSymbolAddress((void**)&Q,   g_Q);
    cudaGetSymbolAddress((void**)&K_,  g_K);
    cudaGetSymbolAddress((void**)&V,   g_V);
    cudaGetSymbolAddress((void**)&Q3,  g_Q3);
    cudaGetSymbolAddress((void**)&K3,  g_K3);
    cudaGetSymbolAddress((void**)&V3t, g_V3t);
    cudaGetSymbolAddress((void**)&S,   g_S);
    cudaGetSymbolAddress((void**)&P3,  g_P3);

    cudaFuncSetAttribute(gemm_f16_mma,
                         cudaFuncAttributeMaxDynamicSharedMemorySize, GEMM_SMEM);

    const float inv_sqrt_d = 0.03608439182435161f;  // 1/sqrt(768)
    const dim3 blk(256);

    // split conversions of inputs
    conv_split<1><<<1024, blk>>>(X, X3, SEQ, DIM);
    conv_split<2><<<512,  blk>>>(Wq, Wq3, DIM, DIM);
    conv_split<2><<<512,  blk>>>(Wk, Wk3, DIM, DIM);
    conv_split<2><<<512,  blk>>>(Wv, Wv3, DIM, DIM);

    // projections: Q/K/V = X @ W^T
    const dim3 gp(DIM / BN, SEQ / BM);   // (6, 64)
    gemm_f16_mma<<<gp, blk, GEMM_SMEM>>>(X3, Wq3, Q,  SEQ, DIM, KE_PROJ, 1.f);
    gemm_f16_mma<<<gp, blk, GEMM_SMEM>>>(X3, Wk3, K_, SEQ, DIM, KE_PROJ, 1.f);
    gemm_f16_mma<<<gp, blk, GEMM_SMEM>>>(X3, Wv3, V,  SEQ, DIM, KE_PROJ, 1.f);

    // split conversions of Q, K; transpose+split V
    conv_split<1><<<1024, blk>>>(Q,  Q3, SEQ, DIM);
    conv_split<2><<<1024, blk>>>(K_, K3, SEQ, DIM);
    conv_split_trans<<<dim3(DIM / 32, SEQ / 32), blk>>>(V, V3t, SEQ, DIM);

    // S = (Q @ K^T) / sqrt(d)
    const dim3 gs(SEQ / BN, SEQ / BM);   // (64, 64)
    gemm_f16_mma<<<gs, blk, GEMM_SMEM>>>(Q3, K3, S, SEQ, SEQ, KE_PROJ, inv_sqrt_d);

    // softmax -> split-fp16 P panels
    softmax_split<<<SEQ, blk>>>(S, P3);

    // O = P @ V
    gemm_f16_mma<<<gp, blk, GEMM_SMEM>>>(P3, V3t, O, SEQ, DIM, KE_PV, 1.f);
}

// round 4
// speedup vs baseline: 6.5677x; 2.1425x over previous
#include <cuda_runtime.h>
#include <cuda_fp16.h>
#include <math.h>
#include <stdint.h>

#define SEQ 8192
#define DIM 768
#define KE_PROJ (3 * DIM)   // 2304  (split-fp16 tripled K, projections only)

// ---------------- scratch (__device__ globals; no allocations allowed) -----
__device__ __align__(128) __half g_X3 [(size_t)SEQ * KE_PROJ];
__device__ __align__(128) __half g_Wq3[(size_t)DIM * KE_PROJ];
__device__ __align__(128) __half g_Wk3[(size_t)DIM * KE_PROJ];
__device__ __align__(128) __half g_Wv3[(size_t)DIM * KE_PROJ];
__device__ __align__(128) __half g_Q16 [(size_t)SEQ * DIM];
__device__ __align__(128) __half g_K16 [(size_t)SEQ * DIM];
__device__ __align__(128) __half g_V16 [(size_t)SEQ * DIM];
__device__ __align__(128) __half g_V16t[(size_t)DIM * SEQ];
__device__ __align__(128) float  g_S  [(size_t)SEQ * SEQ];
__device__ __align__(128) __half g_P16[(size_t)SEQ * SEQ];

// ---------------- helpers ----------------------------------------------------
__device__ __forceinline__ uint32_t smem_u32(const void* p) {
    uint32_t a;
    asm("{ .reg .u64 t; cvta.to.shared.u64 t, %1; cvt.u32.u64 %0, t; }"
        : "=r"(a) : "l"(p));
    return a;
}

#define MMA16816(d, a, b0, b1)                                                 \
    asm volatile(                                                              \
        "mma.sync.aligned.m16n8k16.row.col.f32.f16.f16.f32 "                   \
        "{%0,%1,%2,%3}, {%4,%5,%6,%7}, {%8,%9}, {%0,%1,%2,%3};"                \
        : "+f"((d)[0]), "+f"((d)[1]), "+f"((d)[2]), "+f"((d)[3])               \
        : "r"((a)[0]), "r"((a)[1]), "r"((a)[2]), "r"((a)[3]),                  \
          "r"(b0), "r"(b1))

#define LDSM_X4(r, addr)                                                       \
    asm volatile("ldmatrix.sync.aligned.m8n8.x4.shared.b16 {%0,%1,%2,%3}, [%4];" \
        : "=r"((r)[0]), "=r"((r)[1]), "=r"((r)[2]), "=r"((r)[3]) : "r"(addr))

#define CP_ASYNC16(saddr, gptr)                                                \
    asm volatile("cp.async.cg.shared.global [%0], [%1], 16;"                   \
        :: "r"(saddr), "l"(gptr))

// ---------------- GEMM: C[M,N] = alpha * A[M,Ke] * B[N,Ke]^T  (fp16 in)
// CTA tile 128x128, BK=64 halves, 8 warps each 32x64, double-buffered cp.async.
// OUT_HALF: 0 -> fp32 C, 1 -> fp16 C.
#define BM 128
#define BN 128
#define BKH 64                    // halves per K tile (128 bytes per row)
#define TILE_BYTES (128 * 128)    // 16 KB per operand stage
#define GEMM_SMEM (4 * TILE_BYTES) // 64 KB

template <int OUT_HALF>
__global__ void __launch_bounds__(256, 2)
gemm_f16_mma(const __half* __restrict__ A, const __half* __restrict__ B,
             void* __restrict__ Cv, int M, int N, int Ke, float alpha)
{
    extern __shared__ char smem[];
    const uint32_t sA = smem_u32(smem);                 // 2 stages A
    const uint32_t sB = sA + 2 * TILE_BYTES;            // 2 stages B

    const int tid  = threadIdx.x;
    const int lane = tid & 31;
    const int wid  = tid >> 5;
    const int warp_m = (wid & 3) * 32;
    const int warp_n = (wid >> 2) * 64;
    const int bm = blockIdx.y * BM;
    const int bn = blockIdx.x * BN;
    const int nk = Ke / BKH;

    float acc[2][8][4];
#pragma unroll
    for (int i = 0; i < 2; ++i)
#pragma unroll
        for (int j = 0; j < 8; ++j)
#pragma unroll
            for (int k = 0; k < 4; ++k) acc[i][j][k] = 0.f;

#define LOAD_STAGE(kt, st)                                                     \
    do {                                                                       \
        _Pragma("unroll")                                                      \
        for (int i = 0; i < 4; ++i) {                                          \
            int idx = tid + i * 256;                                           \
            int row = idx >> 3;                                                \
            int ch  = idx & 7;                                                 \
            int pch = ch ^ (row & 7);                                          \
            const __half* gA = A + (size_t)(bm + row) * Ke + (kt) * BKH + ch * 8; \
            CP_ASYNC16(sA + (st) * TILE_BYTES + row * 128 + pch * 16, gA);     \
            const __half* gB = B + (size_t)(bn + row) * Ke + (kt) * BKH + ch * 8; \
            CP_ASYNC16(sB + (st) * TILE_BYTES + row * 128 + pch * 16, gB);     \
        }                                                                      \
        asm volatile("cp.async.commit_group;");                                \
    } while (0)

    LOAD_STAGE(0, 0);

    for (int kt = 0; kt < nk; ++kt) {
        const int st = kt & 1;
        if (kt + 1 < nk) {
            LOAD_STAGE(kt + 1, st ^ 1);
            asm volatile("cp.async.wait_group 1;");
        } else {
            asm volatile("cp.async.wait_group 0;");
        }
        __syncthreads();

        const uint32_t aBase = sA + st * TILE_BYTES;
        const uint32_t bBase = sB + st * TILE_BYTES;
#pragma unroll
        for (int ks = 0; ks < 4; ++ks) {
            uint32_t af[2][4];
#pragma unroll
            for (int mt = 0; mt < 2; ++mt) {
                int row = warp_m + mt * 16 + (lane & 7) + ((lane >> 3) & 1) * 8;
                int ch  = ks * 2 + (lane >> 4);
                uint32_t ad = aBase + row * 128 + ((ch ^ (row & 7)) * 16);
                LDSM_X4(af[mt], ad);
            }
#pragma unroll
            for (int ng = 0; ng < 4; ++ng) {
                int nrow = warp_n + ng * 16 + (lane & 7) + ((lane >> 4) & 1) * 8;
                int ch   = ks * 2 + ((lane >> 3) & 1);
                uint32_t bd = bBase + nrow * 128 + ((ch ^ (nrow & 7)) * 16);
                uint32_t bf[4];
                LDSM_X4(bf, bd);
#pragma unroll
                for (int mt = 0; mt < 2; ++mt) {
                    MMA16816(acc[mt][ng * 2],     af[mt], bf[0], bf[1]);
                    MMA16816(acc[mt][ng * 2 + 1], af[mt], bf[2], bf[3]);
                }
            }
        }
        __syncthreads();
    }

    // epilogue
#pragma unroll
    for (int mt = 0; mt < 2; ++mt) {
        const int r0 = bm + warp_m + mt * 16 + (lane >> 2);
#pragma unroll
        for (int nt = 0; nt < 8; ++nt) {
            const int c = bn + warp_n + nt * 8 + (lane & 3) * 2;
            if (OUT_HALF) {
                __half* C = (__half*)Cv;
                __half2 v0 = __floats2half2_rn(acc[mt][nt][0] * alpha,
                                               acc[mt][nt][1] * alpha);
                __half2 v1 = __floats2half2_rn(acc[mt][nt][2] * alpha,
                                               acc[mt][nt][3] * alpha);
                *(__half2*)(C + (size_t)r0 * N + c)       = v0;
                *(__half2*)(C + (size_t)(r0 + 8) * N + c) = v1;
            } else {
                float* C = (float*)Cv;
                float2 v0 = make_float2(acc[mt][nt][0] * alpha, acc[mt][nt][1] * alpha);
                float2 v1 = make_float2(acc[mt][nt][2] * alpha, acc[mt][nt][3] * alpha);
                *(float2*)(C + (size_t)r0 * N + c)       = v0;
                *(float2*)(C + (size_t)(r0 + 8) * N + c) = v1;
            }
        }
    }
#undef LOAD_STAGE
}

// ---------------- fp32 -> split-fp16 panel conversions ----------------------
__device__ __forceinline__ uint32_t pack2(__half a, __half b) {
    __half2 h = __halves2half2(a, b);
    return *(uint32_t*)&h;
}

// LOPANEL: which of 3 panels holds the low part (A layout: 1, B layout: 2)
template <int LOPANEL>
__global__ void __launch_bounds__(256)
conv_split(const float* __restrict__ src, __half* __restrict__ dst, int rows, int K)
{
    const size_t n4 = (size_t)rows * K / 4;
    const int k4 = K / 4;
    for (size_t i = (size_t)blockIdx.x * 256 + threadIdx.x; i < n4;
         i += (size_t)gridDim.x * 256) {
        const size_t r = i / k4;
        const int c = (int)(i % k4) * 4;
        float4 v = *(const float4*)(src + r * K + c);
        __half h0 = __float2half_rn(v.x), h1 = __float2half_rn(v.y);
        __half h2 = __float2half_rn(v.z), h3 = __float2half_rn(v.w);
        __half l0 = __float2half_rn(v.x - __half2float(h0));
        __half l1 = __float2half_rn(v.y - __half2float(h1));
        __half l2 = __float2half_rn(v.z - __half2float(h2));
        __half l3 = __float2half_rn(v.w - __half2float(h3));
        uint2 hu = make_uint2(pack2(h0, h1), pack2(h2, h3));
        uint2 lu = make_uint2(pack2(l0, l1), pack2(l2, l3));
        __half* d = dst + r * (size_t)(3 * K) + c;
        if (LOPANEL == 1) {
            *(uint2*)(d)         = hu;
            *(uint2*)(d + K)     = lu;
            *(uint2*)(d + 2 * K) = hu;
        } else {
            *(uint2*)(d)         = hu;
            *(uint2*)(d + K)     = hu;
            *(uint2*)(d + 2 * K) = lu;
        }
    }
}

// fp16 transpose: src[R,C] -> dst[C,R]
__global__ void __launch_bounds__(256)
trans_half(const __half* __restrict__ src, __half* __restrict__ dst, int R, int C)
{
    __shared__ __half t[32][33];
    const int tx = threadIdx.x & 31, ty = threadIdx.x >> 5;
    const int bx = blockIdx.x, by = blockIdx.y;
#pragma unroll
    for (int j = 0; j < 32; j += 8)
        t[ty + j][tx] = src[(size_t)(by * 32 + ty + j) * C + bx * 32 + tx];
    __syncthreads();
#pragma unroll
    for (int j = 0; j < 32; j += 8)
        dst[(size_t)(bx * 32 + ty + j) * R + by * 32 + tx] = t[tx][ty + j];
}

// ---------------- softmax over S rows, emitting plain fp16 P ----------------
__global__ void __launch_bounds__(256)
softmax_h(const float* __restrict__ S, __half* __restrict__ P)
{
    __shared__ float buf[SEQ];
    __shared__ float red[256];
    const size_t base = (size_t)blockIdx.x * SEQ;
    const int tid = threadIdx.x;

    float lmax = -INFINITY;
    for (int i = tid; i < SEQ / 4; i += 256) {
        float4 v = *(const float4*)(S + base + (size_t)i * 4);
        *(float4*)&buf[i * 4] = v;
        lmax = fmaxf(lmax, fmaxf(fmaxf(v.x, v.y), fmaxf(v.z, v.w)));
    }
    red[tid] = lmax;
    __syncthreads();
#pragma unroll
    for (int s = 128; s > 0; s >>= 1) {
        if (tid < s) red[tid] = fmaxf(red[tid], red[tid + s]);
        __syncthreads();
    }
    const float m = red[0];
    __syncthreads();

    float lsum = 0.f;
    for (int i = tid; i < SEQ / 4; i += 256) {
        float4 v = *(const float4*)&buf[i * 4];
        v.x = __expf(v.x - m); v.y = __expf(v.y - m);
        v.z = __expf(v.z - m); v.w = __expf(v.w - m);
        *(float4*)&buf[i * 4] = v;
        lsum += v.x + v.y + v.z + v.w;
    }
    red[tid] = lsum;
    __syncthreads();
#pragma unroll
    for (int s = 128; s > 0; s >>= 1) {
        if (tid < s) red[tid] += red[tid + s];
        __syncthreads();
    }
    const float inv = 1.f / red[0];
    __syncthreads();

    __half* d = P + base;
    for (int i = tid; i < SEQ / 4; i += 256) {
        float4 v = *(const float4*)&buf[i * 4];
        uint2 u = make_uint2(
            pack2(__float2half_rn(v.x * inv), __float2half_rn(v.y * inv)),
            pack2(__float2half_rn(v.z * inv), __float2half_rn(v.w * inv)));
        *(uint2*)(d + i * 4) = u;
    }
}

// ---------------------------------------------------------------------------
extern "C" void kernel_launch(void* const* d_in, const int* in_sizes, int n_in,
                              void* d_out, int out_size)
{
    const float* X  = (const float*)d_in[0];
    const float* Wq = (const float*)d_in[1];
    const float* Wk = (const float*)d_in[2];
    const float* Wv = (const float*)d_in[3];
    float* O = (float*)d_out;

    __half *X3, *Wq3, *Wk3, *Wv3, *Q16, *K16, *V16, *V16t, *P16;
    float *S;
    cudaGetSymbolAddress((void**)&X3,   g_X3);
    cudaGetSymbolAddress((void**)&Wq3,  g_Wq3);
    cudaGetSymbolAddress((void**)&Wk3,  g_Wk3);
    cudaGetSymbolAddress((void**)&Wv3,  g_Wv3);
    cudaGetSymbolAddress((void**)&Q16,  g_Q16);
    cudaGetSymbolAddress((void**)&K16,  g_K16);
    cudaGetSymbolAddress((void**)&V16,  g_V16);
    cudaGetSymbolAddress((void**)&V16t, g_V16t);
    cudaGetSymbolAddress((void**)&S,    g_S);
    cudaGetSymbolAddress((void**)&P16,  g_P16);

    cudaFuncSetAttribute(gemm_f16_mma<0>,
                         cudaFuncAttributeMaxDynamicSharedMemorySize, GEMM_SMEM);
    cudaFuncSetAttribute(gemm_f16_mma<1>,
                         cudaFuncAttributeMaxDynamicSharedMemorySize, GEMM_SMEM);

    const float inv_sqrt_d = 0.03608439182435161f;  // 1/sqrt(768)
    const dim3 blk(256);

    // split conversions of inputs (projections stay 3-panel exact-ish)
    conv_split<1><<<1024, blk>>>(X, X3, SEQ, DIM);
    conv_split<2><<<512,  blk>>>(Wq, Wq3, DIM, DIM);
    conv_split<2><<<512,  blk>>>(Wk, Wk3, DIM, DIM);
    conv_split<2><<<512,  blk>>>(Wv, Wv3, DIM, DIM);

    // projections: Q/K/V = X @ W^T, fp16 outputs directly
    const dim3 gp(DIM / BN, SEQ / BM);   // (6, 64)
    gemm_f16_mma<1><<<gp, blk, GEMM_SMEM>>>(X3, Wq3, Q16, SEQ, DIM, KE_PROJ, 1.f);
    gemm_f16_mma<1><<<gp, blk, GEMM_SMEM>>>(X3, Wk3, K16, SEQ, DIM, KE_PROJ, 1.f);
    gemm_f16_mma<1><<<gp, blk, GEMM_SMEM>>>(X3, Wv3, V16, SEQ, DIM, KE_PROJ, 1.f);

    // V transpose (fp16)
    trans_half<<<dim3(DIM / 32, SEQ / 32), blk>>>(V16, V16t, SEQ, DIM);

    // S = (Q @ K^T) / sqrt(d), plain fp16 inputs, fp32 scores
    const dim3 gs(SEQ / BN, SEQ / BM);   // (64, 64)
    gemm_f16_mma<0><<<gs, blk, GEMM_SMEM>>>(Q16, K16, S, SEQ, SEQ, DIM, inv_sqrt_d);

    // softmax -> plain fp16 P
    softmax_h<<<SEQ, blk>>>(S, P16);

    // O = P @ V, fp32 output
    gemm_f16_mma<0><<<gp, blk, GEMM_SMEM>>>(P16, V16t, O, SEQ, DIM, SEQ, 1.f);
}

// round 5
// speedup vs baseline: 7.9494x; 1.2104x over previous
#include <cuda_runtime.h>
#include <cuda_fp16.h>
#include <math.h>
#include <stdint.h>

#define SEQ 8192
#define DIM 768

// ---------------- scratch (__device__ globals; no allocations allowed) -----
__device__ __align__(128) __half g_X16 [(size_t)SEQ * DIM];
__device__ __align__(128) __half g_Wq16[(size_t)DIM * DIM];
__device__ __align__(128) __half g_Wk16[(size_t)DIM * DIM];
__device__ __align__(128) __half g_Wv16[(size_t)DIM * DIM];
__device__ __align__(128) __half g_Q16 [(size_t)SEQ * DIM];
__device__ __align__(128) __half g_K16 [(size_t)SEQ * DIM];
__device__ __align__(128) __half g_V16 [(size_t)SEQ * DIM];
__device__ __align__(128) __half g_V16t[(size_t)DIM * SEQ];
__device__ __align__(128) float  g_S  [(size_t)SEQ * SEQ];
__device__ __align__(128) __half g_P16[(size_t)SEQ * SEQ];

// ---------------- helpers ----------------------------------------------------
__device__ __forceinline__ uint32_t smem_u32(const void* p) {
    uint32_t a;
    asm("{ .reg .u64 t; cvta.to.shared.u64 t, %1; cvt.u32.u64 %0, t; }"
        : "=r"(a) : "l"(p));
    return a;
}

#define MMA16816(d, a, b0, b1)                                                 \
    asm volatile(                                                              \
        "mma.sync.aligned.m16n8k16.row.col.f32.f16.f16.f32 "                   \
        "{%0,%1,%2,%3}, {%4,%5,%6,%7}, {%8,%9}, {%0,%1,%2,%3};"                \
        : "+f"((d)[0]), "+f"((d)[1]), "+f"((d)[2]), "+f"((d)[3])               \
        : "r"((a)[0]), "r"((a)[1]), "r"((a)[2]), "r"((a)[3]),                  \
          "r"(b0), "r"(b1))

#define LDSM_X4(r, addr)                                                       \
    asm volatile("ldmatrix.sync.aligned.m8n8.x4.shared.b16 {%0,%1,%2,%3}, [%4];" \
        : "=r"((r)[0]), "=r"((r)[1]), "=r"((r)[2]), "=r"((r)[3]) : "r"(addr))

#define CP_ASYNC16(saddr, gptr)                                                \
    asm volatile("cp.async.cg.shared.global [%0], [%1], 16;"                   \
        :: "r"(saddr), "l"(gptr))

// ---------------- GEMM: C[M,N] = alpha * A[M,Ke] * B[N,Ke]^T  (fp16 in)
// CTA tile 128x128, BK=64 halves, 8 warps each 32x64, 3-stage cp.async.
// OUT_HALF: 0 -> fp32 C, 1 -> fp16 C.
#define BM 128
#define BN 128
#define BKH 64                     // halves per K tile (128 bytes per row)
#define TILE_BYTES (128 * 128)     // 16 KB per operand stage
#define NSTAGE 3
#define GEMM_SMEM (2 * NSTAGE * TILE_BYTES)   // 96 KB

template <int OUT_HALF>
__global__ void __launch_bounds__(256, 2)
gemm_f16_mma(const __half* __restrict__ A, const __half* __restrict__ B,
             void* __restrict__ Cv, int M, int N, int Ke, float alpha)
{
    extern __shared__ char smem[];
    const uint32_t sA = smem_u32(smem);                    // NSTAGE stages A
    const uint32_t sB = sA + NSTAGE * TILE_BYTES;          // NSTAGE stages B

    const int tid  = threadIdx.x;
    const int lane = tid & 31;
    const int wid  = tid >> 5;
    const int warp_m = (wid & 3) * 32;
    const int warp_n = (wid >> 2) * 64;
    const int bm = blockIdx.y * BM;
    const int bn = blockIdx.x * BN;
    const int nk = Ke / BKH;

    float acc[2][8][4];
#pragma unroll
    for (int i = 0; i < 2; ++i)
#pragma unroll
        for (int j = 0; j < 8; ++j)
#pragma unroll
            for (int k = 0; k < 4; ++k) acc[i][j][k] = 0.f;

#define LOAD_STAGE(kt, st)                                                     \
    do {                                                                       \
        _Pragma("unroll")                                                      \
        for (int i = 0; i < 4; ++i) {                                          \
            int idx = tid + i * 256;                                           \
            int row = idx >> 3;                                                \
            int ch  = idx & 7;                                                 \
            int pch = ch ^ (row & 7);                                          \
            const __half* gA = A + (size_t)(bm + row) * Ke + (kt) * BKH + ch * 8; \
            CP_ASYNC16(sA + (st) * TILE_BYTES + row * 128 + pch * 16, gA);     \
            const __half* gB = B + (size_t)(bn + row) * Ke + (kt) * BKH + ch * 8; \
            CP_ASYNC16(sB + (st) * TILE_BYTES + row * 128 + pch * 16, gB);     \
        }                                                                      \
        asm volatile("cp.async.commit_group;");                                \
    } while (0)

    LOAD_STAGE(0, 0);
    LOAD_STAGE(1, 1);

    for (int kt = 0; kt < nk; ++kt) {
        const int st = kt % NSTAGE;
        if (kt + 1 < nk) {
            asm volatile("cp.async.wait_group 1;");
        } else {
            asm volatile("cp.async.wait_group 0;");
        }
        __syncthreads();
        if (kt + 2 < nk) LOAD_STAGE(kt + 2, (kt + 2) % NSTAGE);

        const uint32_t aBase = sA + st * TILE_BYTES;
        const uint32_t bBase = sB + st * TILE_BYTES;
#pragma unroll
        for (int ks = 0; ks < 4; ++ks) {
            uint32_t af[2][4];
#pragma unroll
            for (int mt = 0; mt < 2; ++mt) {
                int row = warp_m + mt * 16 + (lane & 7) + ((lane >> 3) & 1) * 8;
                int ch  = ks * 2 + (lane >> 4);
                uint32_t ad = aBase + row * 128 + ((ch ^ (row & 7)) * 16);
                LDSM_X4(af[mt], ad);
            }
#pragma unroll
            for (int ng = 0; ng < 4; ++ng) {
                int nrow = warp_n + ng * 16 + (lane & 7) + ((lane >> 4) & 1) * 8;
                int ch   = ks * 2 + ((lane >> 3) & 1);
                uint32_t bd = bBase + nrow * 128 + ((ch ^ (nrow & 7)) * 16);
                uint32_t bf[4];
                LDSM_X4(bf, bd);
#pragma unroll
                for (int mt = 0; mt < 2; ++mt) {
                    MMA16816(acc[mt][ng * 2],     af[mt], bf[0], bf[1]);
                    MMA16816(acc[mt][ng * 2 + 1], af[mt], bf[2], bf[3]);
                }
            }
        }
        __syncthreads();
    }

    // epilogue
#pragma unroll
    for (int mt = 0; mt < 2; ++mt) {
        const int r0 = bm + warp_m + mt * 16 + (lane >> 2);
#pragma unroll
        for (int nt = 0; nt < 8; ++nt) {
            const int c = bn + warp_n + nt * 8 + (lane & 3) * 2;
            if (OUT_HALF) {
                __half* C = (__half*)Cv;
                __half2 v0 = __floats2half2_rn(acc[mt][nt][0] * alpha,
                                               acc[mt][nt][1] * alpha);
                __half2 v1 = __floats2half2_rn(acc[mt][nt][2] * alpha,
                                               acc[mt][nt][3] * alpha);
                *(__half2*)(C + (size_t)r0 * N + c)       = v0;
                *(__half2*)(C + (size_t)(r0 + 8) * N + c) = v1;
            } else {
                float* C = (float*)Cv;
                float2 v0 = make_float2(acc[mt][nt][0] * alpha, acc[mt][nt][1] * alpha);
                float2 v1 = make_float2(acc[mt][nt][2] * alpha, acc[mt][nt][3] * alpha);
                *(float2*)(C + (size_t)r0 * N + c)       = v0;
                *(float2*)(C + (size_t)(r0 + 8) * N + c) = v1;
            }
        }
    }
#undef LOAD_STAGE
}

// ---------------- plain fp32 -> fp16 conversion ------------------------------
__device__ __forceinline__ uint32_t pack2(__half a, __half b) {
    __half2 h = __halves2half2(a, b);
    return *(uint32_t*)&h;
}

__global__ void __launch_bounds__(256)
conv_h(const float* __restrict__ src, __half* __restrict__ dst, size_t n)
{
    const size_t n4 = n / 4;
    for (size_t i = (size_t)blockIdx.x * 256 + threadIdx.x; i < n4;
         i += (size_t)gridDim.x * 256) {
        float4 v = *(const float4*)(src + i * 4);
        uint2 u = make_uint2(
            pack2(__float2half_rn(v.x), __float2half_rn(v.y)),
            pack2(__float2half_rn(v.z), __float2half_rn(v.w)));
        *(uint2*)(dst + i * 4) = u;
    }
}

// fp16 transpose: src[R,C] -> dst[C,R]
__global__ void __launch_bounds__(256)
trans_half(const __half* __restrict__ src, __half* __restrict__ dst, int R, int C)
{
    __shared__ __half t[32][33];
    const int tx = threadIdx.x & 31, ty = threadIdx.x >> 5;
    const int bx = blockIdx.x, by = blockIdx.y;
#pragma unroll
    for (int j = 0; j < 32; j += 8)
        t[ty + j][tx] = src[(size_t)(by * 32 + ty + j) * C + bx * 32 + tx];
    __syncthreads();
#pragma unroll
    for (int j = 0; j < 32; j += 8)
        dst[(size_t)(bx * 32 + ty + j) * R + by * 32 + tx] = t[tx][ty + j];
}

// ---------------- softmax over S rows, emitting plain fp16 P ----------------
__global__ void __launch_bounds__(256)
softmax_h(const float* __restrict__ S, __half* __restrict__ P)
{
    __shared__ float buf[SEQ];
    __shared__ float red[256];
    const size_t base = (size_t)blockIdx.x * SEQ;
    const int tid = threadIdx.x;

    float lmax = -INFINITY;
    for (int i = tid; i < SEQ / 4; i += 256) {
        float4 v = *(const float4*)(S + base + (size_t)i * 4);
        *(float4*)&buf[i * 4] = v;
        lmax = fmaxf(lmax, fmaxf(fmaxf(v.x, v.y), fmaxf(v.z, v.w)));
    }
    red[tid] = lmax;
    __syncthreads();
#pragma unroll
    for (int s = 128; s > 0; s >>= 1) {
        if (tid < s) red[tid] = fmaxf(red[tid], red[tid + s]);
        __syncthreads();
    }
    const float m = red[0];
    __syncthreads();

    float lsum = 0.f;
    for (int i = tid; i < SEQ / 4; i += 256) {
        float4 v = *(const float4*)&buf[i * 4];
        v.x = __expf(v.x - m); v.y = __expf(v.y - m);
        v.z = __expf(v.z - m); v.w = __expf(v.w - m);
        *(float4*)&buf[i * 4] = v;
        lsum += v.x + v.y + v.z + v.w;
    }
    red[tid] = lsum;
    __syncthreads();
#pragma unroll
    for (int s = 128; s > 0; s >>= 1) {
        if (tid < s) red[tid] += red[tid + s];
        __syncthreads();
    }
    const float inv = 1.f / red[0];
    __syncthreads();

    __half* d = P + base;
    for (int i = tid; i < SEQ / 4; i += 256) {
        float4 v = *(const float4*)&buf[i * 4];
        uint2 u = make_uint2(
            pack2(__float2half_rn(v.x * inv), __float2half_rn(v.y * inv)),
            pack2(__float2half_rn(v.z * inv), __float2half_rn(v.w * inv)));
        *(uint2*)(d + i * 4) = u;
    }
}

// ---------------------------------------------------------------------------
extern "C" void kernel_launch(void* const* d_in, const int* in_sizes, int n_in,
                              void* d_out, int out_size)
{
    const float* X  = (const float*)d_in[0];
    const float* Wq = (const float*)d_in[1];
    const float* Wk = (const float*)d_in[2];
    const float* Wv = (const float*)d_in[3];
    float* O = (float*)d_out;

    __half *X16, *Wq16, *Wk16, *Wv16, *Q16, *K16, *V16, *V16t, *P16;
    float *S;
    cudaGetSymbolAddress((void**)&X16,  g_X16);
    cudaGetSymbolAddress((void**)&Wq16, g_Wq16);
    cudaGetSymbolAddress((void**)&Wk16, g_Wk16);
    cudaGetSymbolAddress((void**)&Wv16, g_Wv16);
    cudaGetSymbolAddress((void**)&Q16,  g_Q16);
    cudaGetSymbolAddress((void**)&K16,  g_K16);
    cudaGetSymbolAddress((void**)&V16,  g_V16);
    cudaGetSymbolAddress((void**)&V16t, g_V16t);
    cudaGetSymbolAddress((void**)&S,    g_S);
    cudaGetSymbolAddress((void**)&P16,  g_P16);

    cudaFuncSetAttribute(gemm_f16_mma<0>,
                         cudaFuncAttributeMaxDynamicSharedMemorySize, GEMM_SMEM);
    cudaFuncSetAttribute(gemm_f16_mma<1>,
                         cudaFuncAttributeMaxDynamicSharedMemorySize, GEMM_SMEM);

    const float inv_sqrt_d = 0.03608439182435161f;  // 1/sqrt(768)
    const dim3 blk(256);

    // plain fp16 conversions
    conv_h<<<592, blk>>>(X,  X16,  (size_t)SEQ * DIM);
    conv_h<<<296, blk>>>(Wq, Wq16, (size_t)DIM * DIM);
    conv_h<<<296, blk>>>(Wk, Wk16, (size_t)DIM * DIM);
    conv_h<<<296, blk>>>(Wv, Wv16, (size_t)DIM * DIM);

    // projections: Q/K/V = X @ W^T, fp16 outputs
    const dim3 gp(DIM / BN, SEQ / BM);   // (6, 64)
    gemm_f16_mma<1><<<gp, blk, GEMM_SMEM>>>(X16, Wq16, Q16, SEQ, DIM, DIM, 1.f);
    gemm_f16_mma<1><<<gp, blk, GEMM_SMEM>>>(X16, Wk16, K16, SEQ, DIM, DIM, 1.f);
    gemm_f16_mma<1><<<gp, blk, GEMM_SMEM>>>(X16, Wv16, V16, SEQ, DIM, DIM, 1.f);

    // V transpose (fp16)
    trans_half<<<dim3(DIM / 32, SEQ / 32), blk>>>(V16, V16t, SEQ, DIM);

    // S = (Q @ K^T) / sqrt(d), fp32 scores
    const dim3 gs(SEQ / BN, SEQ / BM);   // (64, 64)
    gemm_f16_mma<0><<<gs, blk, GEMM_SMEM>>>(Q16, K16, S, SEQ, SEQ, DIM, inv_sqrt_d);

    // softmax -> plain fp16 P
    softmax_h<<<SEQ, blk>>>(S, P16);

    // O = P @ V, fp32 output
    gemm_f16_mma<0><<<gp, blk, GEMM_SMEM>>>(P16, V16t, O, SEQ, DIM, SEQ, 1.f);
}

// round 6
// speedup vs baseline: 8.0979x; 1.0187x over previous
#include <cuda_runtime.h>
#include <cuda_fp16.h>
#include <math.h>
#include <stdint.h>

#define SEQ 8192
#define DIM 768
#define DIM3 (3 * DIM)   // 2304

// ---------------- scratch (__device__ globals; no allocations allowed) -----
__device__ __align__(128) __half g_X16 [(size_t)SEQ * DIM];
__device__ __align__(128) __half g_Wc16[(size_t)DIM3 * DIM];       // [Wq;Wk;Wv]
__device__ __align__(128) __half g_QKV [(size_t)SEQ * DIM3];       // packed Q|K|V
__device__ __align__(128) __half g_V16t[(size_t)DIM * SEQ];
__device__ __align__(128) float  g_S   [(size_t)SEQ * SEQ];
__device__ __align__(128) __half g_P16 [(size_t)SEQ * SEQ];
__device__ __align__(128) float  g_Opart[2][(size_t)SEQ * DIM];    // PV split-K partials

// ---------------- helpers ----------------------------------------------------
__device__ __forceinline__ uint32_t smem_u32(const void* p) {
    uint32_t a;
    asm("{ .reg .u64 t; cvta.to.shared.u64 t, %1; cvt.u32.u64 %0, t; }"
        : "=r"(a) : "l"(p));
    return a;
}

#define MMA16816(d, a, b0, b1)                                                 \
    asm volatile(                                                              \
        "mma.sync.aligned.m16n8k16.row.col.f32.f16.f16.f32 "                   \
        "{%0,%1,%2,%3}, {%4,%5,%6,%7}, {%8,%9}, {%0,%1,%2,%3};"                \
        : "+f"((d)[0]), "+f"((d)[1]), "+f"((d)[2]), "+f"((d)[3])               \
        : "r"((a)[0]), "r"((a)[1]), "r"((a)[2]), "r"((a)[3]),                  \
          "r"(b0), "r"(b1))

#define LDSM_X4(r, addr)                                                       \
    asm volatile("ldmatrix.sync.aligned.m8n8.x4.shared.b16 {%0,%1,%2,%3}, [%4];" \
        : "=r"((r)[0]), "=r"((r)[1]), "=r"((r)[2]), "=r"((r)[3]) : "r"(addr))

#define CP_ASYNC16(saddr, gptr)                                                \
    asm volatile("cp.async.cg.shared.global [%0], [%1], 16;"                   \
        :: "r"(saddr), "l"(gptr))

// ---------------- GEMM: C[M,N] = alpha * A[M,*] * B[N,*]^T  (fp16 in)
// CTA tile 128x128, BK=64 halves, 8 warps each 32x64, 3-stage cp.async.
// Explicit row strides lda/ldb/ldc (elements). gridDim.z = K-splits: split z
// covers K range [z*Ke, (z+1)*Ke) and writes C + z*csplit.
// OUT_HALF: 0 -> fp32 C, 1 -> fp16 C.
#define BM 128
#define BN 128
#define BKH 64                     // halves per K tile (128 bytes per row)
#define TILE_BYTES (128 * 128)     // 16 KB per operand stage
#define NSTAGE 3
#define GEMM_SMEM (2 * NSTAGE * TILE_BYTES)   // 96 KB

template <int OUT_HALF>
__global__ void __launch_bounds__(256, 2)
gemm_f16_mma(const __half* __restrict__ A, const __half* __restrict__ B,
             void* __restrict__ Cv, int N, int Ke,
             int lda, int ldb, int ldc, float alpha, size_t csplit)
{
    extern __shared__ char smem[];
    const uint32_t sA = smem_u32(smem);                    // NSTAGE stages A
    const uint32_t sB = sA + NSTAGE * TILE_BYTES;          // NSTAGE stages B

    const int tid  = threadIdx.x;
    const int lane = tid & 31;
    const int wid  = tid >> 5;
    const int warp_m = (wid & 3) * 32;
    const int warp_n = (wid >> 2) * 64;
    const int bm = blockIdx.y * BM;
    const int bn = blockIdx.x * BN;
    const int koff = blockIdx.z * Ke;
    const int nk = Ke / BKH;

    float acc[2][8][4];
#pragma unroll
    for (int i = 0; i < 2; ++i)
#pragma unroll
        for (int j = 0; j < 8; ++j)
#pragma unroll
            for (int k = 0; k < 4; ++k) acc[i][j][k] = 0.f;

#define LOAD_STAGE(kt, st)                                                     \
    do {                                                                       \
        _Pragma("unroll")                                                      \
        for (int i = 0; i < 4; ++i) {                                          \
            int idx = tid + i * 256;                                           \
            int row = idx >> 3;                                                \
            int ch  = idx & 7;                                                 \
            int pch = ch ^ (row & 7);                                          \
            const __half* gA = A + (size_t)(bm + row) * lda + koff + (kt) * BKH + ch * 8; \
            CP_ASYNC16(sA + (st) * TILE_BYTES + row * 128 + pch * 16, gA);     \
            const __half* gB = B + (size_t)(bn + row) * ldb + koff + (kt) * BKH + ch * 8; \
            CP_ASYNC16(sB + (st) * TILE_BYTES + row * 128 + pch * 16, gB);     \
        }                                                                      \
        asm volatile("cp.async.commit_group;");                                \
    } while (0)

    LOAD_STAGE(0, 0);
    LOAD_STAGE(1, 1);

    for (int kt = 0; kt < nk; ++kt) {
        const int st = kt % NSTAGE;
        if (kt + 1 < nk) {
            asm volatile("cp.async.wait_group 1;");
        } else {
            asm volatile("cp.async.wait_group 0;");
        }
        __syncthreads();
        if (kt + 2 < nk) LOAD_STAGE(kt + 2, (kt + 2) % NSTAGE);

        const uint32_t aBase = sA + st * TILE_BYTES;
        const uint32_t bBase = sB + st * TILE_BYTES;
#pragma unroll
        for (int ks = 0; ks < 4; ++ks) {
            uint32_t af[2][4];
#pragma unroll
            for (int mt = 0; mt < 2; ++mt) {
                int row = warp_m + mt * 16 + (lane & 7) + ((lane >> 3) & 1) * 8;
                int ch  = ks * 2 + (lane >> 4);
                uint32_t ad = aBase + row * 128 + ((ch ^ (row & 7)) * 16);
                LDSM_X4(af[mt], ad);
            }
#pragma unroll
            for (int ng = 0; ng < 4; ++ng) {
                int nrow = warp_n + ng * 16 + (lane & 7) + ((lane >> 4) & 1) * 8;
                int ch   = ks * 2 + ((lane >> 3) & 1);
                uint32_t bd = bBase + nrow * 128 + ((ch ^ (nrow & 7)) * 16);
                uint32_t bf[4];
                LDSM_X4(bf, bd);
#pragma unroll
                for (int mt = 0; mt < 2; ++mt) {
                    MMA16816(acc[mt][ng * 2],     af[mt], bf[0], bf[1]);
                    MMA16816(acc[mt][ng * 2 + 1], af[mt], bf[2], bf[3]);
                }
            }
        }
        __syncthreads();
    }

    // epilogue
#pragma unroll
    for (int mt = 0; mt < 2; ++mt) {
        const int r0 = bm + warp_m + mt * 16 + (lane >> 2);
#pragma unroll
        for (int nt = 0; nt < 8; ++nt) {
            const int c = bn + warp_n + nt * 8 + (lane & 3) * 2;
            if (OUT_HALF) {
                __half* C = (__half*)Cv + blockIdx.z * csplit;
                __half2 v0 = __floats2half2_rn(acc[mt][nt][0] * alpha,
                                               acc[mt][nt][1] * alpha);
                __half2 v1 = __floats2half2_rn(acc[mt][nt][2] * alpha,
                                               acc[mt][nt][3] * alpha);
                *(__half2*)(C + (size_t)r0 * ldc + c)       = v0;
                *(__half2*)(C + (size_t)(r0 + 8) * ldc + c) = v1;
            } else {
                float* C = (float*)Cv + blockIdx.z * csplit;
                float2 v0 = make_float2(acc[mt][nt][0] * alpha, acc[mt][nt][1] * alpha);
                float2 v1 = make_float2(acc[mt][nt][2] * alpha, acc[mt][nt][3] * alpha);
                *(float2*)(C + (size_t)r0 * ldc + c)       = v0;
                *(float2*)(C + (size_t)(r0 + 8) * ldc + c) = v1;
            }
        }
    }
#undef LOAD_STAGE
}

// ---------------- plain fp32 -> fp16 conversion ------------------------------
__device__ __forceinline__ uint32_t pack2(__half a, __half b) {
    __half2 h = __halves2half2(a, b);
    return *(uint32_t*)&h;
}

__global__ void __launch_bounds__(256)
conv_h(const float* __restrict__ src, __half* __restrict__ dst, size_t n)
{
    const size_t n4 = n / 4;
    for (size_t i = (size_t)blockIdx.x * 256 + threadIdx.x; i < n4;
         i += (size_t)gridDim.x * 256) {
        float4 v = *(const float4*)(src + i * 4);
        uint2 u = make_uint2(
            pack2(__float2half_rn(v.x), __float2half_rn(v.y)),
            pack2(__float2half_rn(v.z), __float2half_rn(v.w)));
        *(uint2*)(dst + i * 4) = u;
    }
}

// fp16 transpose with src row stride: src[R x C, stride srcld] -> dst[C x R]
__global__ void __launch_bounds__(256)
trans_half(const __half* __restrict__ src, __half* __restrict__ dst,
           int R, int C, int srcld)
{
    __shared__ __half t[32][33];
    const int tx = threadIdx.x & 31, ty = threadIdx.x >> 5;
    const int bx = blockIdx.x, by = blockIdx.y;
#pragma unroll
    for (int j = 0; j < 32; j += 8)
        t[ty + j][tx] = src[(size_t)(by * 32 + ty + j) * srcld + bx * 32 + tx];
    __syncthreads();
#pragma unroll
    for (int j = 0; j < 32; j += 8)
        dst[(size_t)(bx * 32 + ty + j) * R + by * 32 + tx] = t[tx][ty + j];
}

// ---------------- softmax over S rows, emitting plain fp16 P ----------------
__global__ void __launch_bounds__(256)
softmax_h(const float* __restrict__ S, __half* __restrict__ P)
{
    __shared__ float buf[SEQ];
    __shared__ float red[256];
    const size_t base = (size_t)blockIdx.x * SEQ;
    const int tid = threadIdx.x;

    float lmax = -INFINITY;
    for (int i = tid; i < SEQ / 4; i += 256) {
        float4 v = *(const float4*)(S + base + (size_t)i * 4);
        *(float4*)&buf[i * 4] = v;
        lmax = fmaxf(lmax, fmaxf(fmaxf(v.x, v.y), fmaxf(v.z, v.w)));
    }
    red[tid] = lmax;
    __syncthreads();
#pragma unroll
    for (int s = 128; s > 0; s >>= 1) {
        if (tid < s) red[tid] = fmaxf(red[tid], red[tid + s]);
        __syncthreads();
    }
    const float m = red[0];
    __syncthreads();

    float lsum = 0.f;
    for (int i = tid; i < SEQ / 4; i += 256) {
        float4 v = *(const float4*)&buf[i * 4];
        v.x = __expf(v.x - m); v.y = __expf(v.y - m);
        v.z = __expf(v.z - m); v.w = __expf(v.w - m);
        *(float4*)&buf[i * 4] = v;
        lsum += v.x + v.y + v.z + v.w;
    }
    red[tid] = lsum;
    __syncthreads();
#pragma unroll
    for (int s = 128; s > 0; s >>= 1) {
        if (tid < s) red[tid] += red[tid + s];
        __syncthreads();
    }
    const float inv = 1.f / red[0];
    __syncthreads();

    __half* d = P + base;
    for (int i = tid; i < SEQ / 4; i += 256) {
        float4 v = *(const float4*)&buf[i * 4];
        uint2 u = make_uint2(
            pack2(__float2half_rn(v.x * inv), __float2half_rn(v.y * inv)),
            pack2(__float2half_rn(v.z * inv), __float2half_rn(v.w * inv)));
        *(uint2*)(d + i * 4) = u;
    }
}

// ---------------- split-K reduction: O = A0 + A1 -----------------------------
__global__ void __launch_bounds__(256)
add2_f32(const float* __restrict__ a, const float* __restrict__ b,
         float* __restrict__ o, size_t n)
{
    const size_t n4 = n / 4;
    for (size_t i = (size_t)blockIdx.x * 256 + threadIdx.x; i < n4;
         i += (size_t)gridDim.x * 256) {
        float4 x = *(const float4*)(a + i * 4);
        float4 y = *(const float4*)(b + i * 4);
        x.x += y.x; x.y += y.y; x.z += y.z; x.w += y.w;
        *(float4*)(o + i * 4) = x;
    }
}

// ---------------------------------------------------------------------------
extern "C" void kernel_launch(void* const* d_in, const int* in_sizes, int n_in,
                              void* d_out, int out_size)
{
    const float* X  = (const float*)d_in[0];
    const float* Wq = (const float*)d_in[1];
    const float* Wk = (const float*)d_in[2];
    const float* Wv = (const float*)d_in[3];
    float* O = (float*)d_out;

    __half *X16, *Wc16, *QKV, *V16t, *P16;
    float *S, *Op;
    cudaGetSymbolAddress((void**)&X16,  g_X16);
    cudaGetSymbolAddress((void**)&Wc16, g_Wc16);
    cudaGetSymbolAddress((void**)&QKV,  g_QKV);
    cudaGetSymbolAddress((void**)&V16t, g_V16t);
    cudaGetSymbolAddress((void**)&S,    g_S);
    cudaGetSymbolAddress((void**)&P16,  g_P16);
    cudaGetSymbolAddress((void**)&Op,   g_Opart);

    cudaFuncSetAttribute(gemm_f16_mma<0>,
                         cudaFuncAttributeMaxDynamicSharedMemorySize, GEMM_SMEM);
    cudaFuncSetAttribute(gemm_f16_mma<1>,
                         cudaFuncAttributeMaxDynamicSharedMemorySize, GEMM_SMEM);

    const float inv_sqrt_d = 0.03608439182435161f;  // 1/sqrt(768)
    const dim3 blk(256);
    const size_t WSZ = (size_t)DIM * DIM;

    // plain fp16 conversions; W concatenated [Wq;Wk;Wv] -> [2304 x 768]
    conv_h<<<592, blk>>>(X,  X16, (size_t)SEQ * DIM);
    conv_h<<<296, blk>>>(Wq, Wc16,           WSZ);
    conv_h<<<296, blk>>>(Wk, Wc16 + WSZ,     WSZ);
    conv_h<<<296, blk>>>(Wv, Wc16 + 2 * WSZ, WSZ);

    // fused projection: QKV[8192 x 2304] = X @ Wc^T  (single launch, 1152 CTAs)
    gemm_f16_mma<1><<<dim3(DIM3 / BN, SEQ / BM, 1), blk, GEMM_SMEM>>>(
        X16, Wc16, QKV, DIM3, DIM, DIM, DIM, DIM3, 1.f, 0);

    // S = (Q @ K^T) / sqrt(d): Q/K are strided slices of QKV
    gemm_f16_mma<0><<<dim3(SEQ / BN, SEQ / BM, 1), blk, GEMM_SMEM>>>(
        QKV, QKV + DIM, S, SEQ, DIM, DIM3, DIM3, SEQ, inv_sqrt_d, 0);

    // V transpose (strided slice of QKV) -> V16t [768 x 8192]
    trans_half<<<dim3(DIM / 32, SEQ / 32), blk>>>(QKV + 2 * DIM, V16t,
                                                  SEQ, DIM, DIM3);

    // softmax -> plain fp16 P
    softmax_h<<<SEQ, blk>>>(S, P16);

    // O = P @ V: split-K=2 via gridDim.z (768 CTAs in one launch)
    gemm_f16_mma<0><<<dim3(DIM / BN, SEQ / BM, 2), blk, GEMM_SMEM>>>(
        P16, V16t, Op, DIM, SEQ / 2, SEQ, SEQ, DIM, 1.f, (size_t)SEQ * DIM);

    // O = partial0 + partial1
    add2_f32<<<1024, blk>>>(Op, Op + (size_t)SEQ * DIM, O, (size_t)SEQ * DIM);
}